// round 2
// baseline (speedup 1.0000x reference)
#include <cuda_runtime.h>

#define IMG   4096
#define TW    64                 // tile width  (x)
#define TH    128                // tile height (y)
#define KY    32                 // y-outputs per thread
#define HALO  7
#define RW    (TW + 2*HALO)      // 78 raw columns
#define SW    (RW + 1)           // 79 row-prefix entries (leading zero)
#define ROWS  (TH + 2*HALO)      // 142 smem rows
#define STRIDE 81                // 17L mod 32 distinct -> conflict-free column access

__global__ __launch_bounds__(256, 4) void meanconv_rps_kernel(
    const float* __restrict__ x,
    const float* __restrict__ mask,
    float* __restrict__ out)
{
    __shared__ float R[ROWS * STRIDE];   // 142*81*4 = 46.0 KB

    const int t   = threadIdx.x;
    const int gx0 = blockIdx.x * TW;
    const int gy0 = blockIdx.y * TH;

    // ---- Load clamped raw tile (replicate padding == index clamp) ----
    for (int idx = t; idx < ROWS * RW; idx += 256) {
        int r = idx / RW;
        int c = idx - r * RW;
        int gy = gy0 - HALO + r; gy = min(max(gy, 0), IMG - 1);
        int gx = gx0 - HALO + c; gx = min(max(gx, 0), IMG - 1);
        R[r * STRIDE + 1 + c] = x[gy * IMG + gx];
    }
    __syncthreads();

    // ---- Horizontal prefix sum per row (thread per row; FADD chain) ----
    if (t < ROWS) {
        float* row = &R[t * STRIDE];
        row[0] = 0.0f;
        float acc = 0.0f;
        #pragma unroll 6
        for (int c = 1; c < SW; c++) { acc += row[c]; row[c] = acc; }
    }
    __syncthreads();

    // ---- Query: per-thread column sweep with register ring buffers ----
    const int tx = t & (TW - 1);
    const int y0 = (t >> 6) * KY;            // 0,32,64,96

    float a[KY];
    #pragma unroll
    for (int j = 0; j < KY; j++) a[j] = 0.0f;

    // rs_p(r) = Rb[r*STRIDE + p] - Rb[r*STRIDE - 1 - p], Rb centered at column tx+8
    const float* Rb = &R[tx + 8];

    #pragma unroll
    for (int p = 1; p <= 7; p++) {
        const int   L = 2 * p + 1;
        const float w = 1.0f / (7.0f * (float)(L * L));
        float ring[15];
        float B = 0.0f;

        // initialize window for y = y0: rows y0-p .. y0+p (smem row = y + HALO)
        #pragma unroll
        for (int i = 0; i < L; i++) {
            const int r = y0 + HALO - p + i;
            float rs = Rb[r * STRIDE + p] - Rb[r * STRIDE - 1 - p];
            ring[i] = rs;
            B += rs;
        }
        a[0] += w * B;

        // slide window down; each rs loaded exactly once
        #pragma unroll
        for (int j = 1; j < KY; j++) {
            const int r = y0 + HALO + j + p;
            float rs = Rb[r * STRIDE + p] - Rb[r * STRIDE - 1 - p];
            const int slot = (j - 1) % L;     // compile-time constant (fully unrolled)
            B += rs - ring[slot];
            ring[slot] = rs;
            a[j] += w * B;
        }
    }

    // ---- Masked store (coalesced) ----
    #pragma unroll 4
    for (int j = 0; j < KY; j++) {
        const int g = (gy0 + y0 + j) * IMG + (gx0 + tx);
        out[g] = a[j] * mask[g];
    }
}

extern "C" void kernel_launch(void* const* d_in, const int* in_sizes, int n_in,
                              void* d_out, int out_size)
{
    const float* x    = (const float*)d_in[0];
    const float* mask = (const float*)d_in[1];
    float* out        = (float*)d_out;

    dim3 grid(IMG / TW, IMG / TH);   // 64 x 32 tiles
    meanconv_rps_kernel<<<grid, 256>>>(x, mask, out);
}